// round 14
// baseline (speedup 1.0000x reference)
#include <cuda_runtime.h>
#include <cstdint>

#define T_LEN 1024
#define B_SZ  128
#define D_IN  32
#define H_DIM 64
#define W_DIM 128
#define C_DIM 33     // D_IN + 1
#define O_DIM 2112   // H_DIM * C_DIM
#define P_CL  8      // cluster size (output partition)
#define HSL   8      // heads per CTA slice
#define OSL   264    // outputs per CTA slice (8 h * 33 c)
#define OSL_MAIN 256 // uniform part; 8-output tail warp-reduced
#define BA    8      // batches per cluster
#define NTHR  256
#define NCTA  128    // 16 clusters * 8

typedef unsigned long long u64;

// Prepared weights: transposed vW2 and transposed-paired vW0
__device__ float  g_vW2T[W_DIM * O_DIM];   // [k][o]
__device__ float2 g_vW0pT[32 * W_DIM];     // [p][j] = (vW0[j][1+2p], vW0[j][2+2p])
__device__ float  g_vW0c[W_DIM];           // vW0[j][0] (t column)

__global__ void cde_prep_kernel(const float* __restrict__ vW2,
                                const float* __restrict__ vW0) {
    int idx = blockIdx.x * blockDim.x + threadIdx.x;
    if (idx < W_DIM * O_DIM) {
        int k = idx / O_DIM, o = idx - k * O_DIM;
        g_vW2T[idx] = vW2[o * W_DIM + k];
    }
    if (idx < 32 * W_DIM) {
        int p = idx >> 7, j = idx & 127;
        g_vW0pT[idx] = make_float2(vW0[j * 65 + 1 + 2 * p], vW0[j * 65 + 2 + 2 * p]);
    }
    if (idx < W_DIM) g_vW0c[idx] = vW0[idx * 65];
}

struct __align__(16) Smem {
    float wsl[W_DIM * OSL];    // 135168 B  vW2T slice [k][264], resident
    float vW1p[W_DIM * 130];   //  66560 B  [j][k] stride 130 (conflict-free LDS.64)
    float vb0[W_DIM];
    float vb1[W_DIM];
    float vb2s[OSL];
    float z1[BA][132];
    float z2c[BA][132];        // z2 per batch (tail)
    float z2q[W_DIM][BA];      // [k] -> 8 batch z values (32B rows)
    float yh[2][BA][66];       // FULL yhat, parity double-buffered
    float vloc[BA][OSL];       // v slice per batch
    float dxv[2][BA][34];      // parity double-buffered dx
    float red[BA][HSL];
    float pbuf[P_CL][BA];
};  // total 231712 B <= 232448

__device__ __forceinline__ void ffma2(u64& d, u64 a, u64 b) {
    asm("fma.rn.f32x2 %0, %1, %2, %0;" : "+l"(d) : "l"(a), "l"(b));
}
__device__ __forceinline__ u64 pack2(float x, float y) {
    u64 r; asm("mov.b64 %0, {%1, %2};" : "=l"(r) : "f"(x), "f"(y)); return r;
}
__device__ __forceinline__ float2 unpack2(u64 v) {
    float2 r; asm("mov.b64 {%0, %1}, %2;" : "=f"(r.x), "=f"(r.y) : "l"(v)); return r;
}
__device__ __forceinline__ uint32_t s2u(const void* p) {
    uint32_t a;
    asm("{ .reg .u64 t; cvta.to.shared.u64 t, %1; cvt.u32.u64 %0, t; }" : "=r"(a) : "l"(p));
    return a;
}
__device__ __forceinline__ uint32_t cl_rank() {
    uint32_t r; asm("mov.u32 %0, %%cluster_ctarank;" : "=r"(r)); return r;
}
__device__ __forceinline__ void st_cluster(uint32_t addr, uint32_t rank, float v) {
    asm volatile(
        "{ .reg .b32 r; mapa.shared::cluster.u32 r, %0, %1; st.shared::cluster.f32 [r], %2; }"
        :: "r"(addr), "r"(rank), "f"(v) : "memory");
}
#define CLUSTER_SYNC() do { \
    asm volatile("barrier.cluster.arrive.aligned;" ::: "memory"); \
    asm volatile("barrier.cluster.wait.aligned;" ::: "memory"); \
} while (0)

__device__ __forceinline__ float lipswish_f(float x) {
    float sg = __fdividef(1.0f, 1.0f + __expf(-x));
    return 0.909f * x * sg;
}
__device__ __forceinline__ float tanh_f(float x) {
    float e = __expf(2.0f * x);
    return 1.0f - __fdividef(2.0f, e + 1.0f);
}

// v slice = tanh(vW2[slice] @ lipswish(vW1 @ lipswish(vW0 @ [t, yhat] + vb0) + vb1) + vb2[slice])
// for the 8 batches of this cluster; weights smem/L2-resident. 256 threads.
__device__ __forceinline__ void vf_eval(Smem* sm, int tid, int rank, float t1, int par,
                                        const float* __restrict__ vW2) {
    const int j  = tid & 127;   // neuron / output-pair index
    const int bq = tid >> 7;    // batch quartet: batches 4bq..4bq+3

    // ---- layer 1 (65 -> 128): coalesced global paired weights, 4 batches/thread ----
    {
        const u64* y0 = (const u64*)sm->yh[par][4 * bq + 0];
        const u64* y1 = (const u64*)sm->yh[par][4 * bq + 1];
        const u64* y2 = (const u64*)sm->yh[par][4 * bq + 2];
        const u64* y3 = (const u64*)sm->yh[par][4 * bq + 3];
        u64 a0 = 0, a1 = 0, a2 = 0, a3 = 0;
        #pragma unroll 8
        for (int p = 0; p < 32; p++) {
            float2 wf = __ldg(&g_vW0pT[p * W_DIM + j]);   // coalesced LDG.64
            u64 w = pack2(wf.x, wf.y);
            ffma2(a0, w, y0[p]); ffma2(a1, w, y1[p]);
            ffma2(a2, w, y2[p]); ffma2(a3, w, y3[p]);
        }
        float base = sm->vb0[j] + t1 * g_vW0c[j];
        float2 r;
        r = unpack2(a0); sm->z1[4 * bq + 0][j] = lipswish_f(base + r.x + r.y);
        r = unpack2(a1); sm->z1[4 * bq + 1][j] = lipswish_f(base + r.x + r.y);
        r = unpack2(a2); sm->z1[4 * bq + 2][j] = lipswish_f(base + r.x + r.y);
        r = unpack2(a3); sm->z1[4 * bq + 3][j] = lipswish_f(base + r.x + r.y);
    }
    __syncthreads();

    // ---- layer 2 (128 -> 128): smem weights, 4 batches/thread ----
    {
        const u64* wp = (const u64*)&sm->vW1p[j * 130];
        const u64* z0 = (const u64*)sm->z1[4 * bq + 0];
        const u64* z1p = (const u64*)sm->z1[4 * bq + 1];
        const u64* z2p = (const u64*)sm->z1[4 * bq + 2];
        const u64* z3p = (const u64*)sm->z1[4 * bq + 3];
        u64 a0 = 0, a1 = 0, a2 = 0, a3 = 0;
        #pragma unroll 8
        for (int p = 0; p < 64; p++) {
            u64 w = wp[p];
            ffma2(a0, w, z0[p]);  ffma2(a1, w, z1p[p]);
            ffma2(a2, w, z2p[p]); ffma2(a3, w, z3p[p]);
        }
        float bb = sm->vb1[j];
        float2 r;
        r = unpack2(a0); float v0 = lipswish_f(bb + r.x + r.y);
        r = unpack2(a1); float v1 = lipswish_f(bb + r.x + r.y);
        r = unpack2(a2); float v2 = lipswish_f(bb + r.x + r.y);
        r = unpack2(a3); float v3 = lipswish_f(bb + r.x + r.y);
        sm->z2c[4 * bq + 0][j] = v0;  sm->z2q[j][4 * bq + 0] = v0;
        sm->z2c[4 * bq + 1][j] = v1;  sm->z2q[j][4 * bq + 1] = v1;
        sm->z2c[4 * bq + 2][j] = v2;  sm->z2q[j][4 * bq + 2] = v2;
        sm->z2c[4 * bq + 3][j] = v3;  sm->z2q[j][4 * bq + 3] = v3;
    }
    __syncthreads();

    // ---- layer 3 main: slice outputs [0,256), 2 outputs x 4 batches per thread,
    //      weights from resident smem (pure LDS, no global latency) ----
    {
        u64 acc00 = 0, acc01 = 0, acc10 = 0, acc11 = 0;
        #pragma unroll 8
        for (int k = 0; k < W_DIM; k++) {
            float2 w2 = *(const float2*)&sm->wsl[k * OSL + 2 * j];       // LDS.64
            ulonglong2 zq = *(const ulonglong2*)&sm->z2q[k][4 * bq];     // LDS.128 bcast
            u64 w0 = pack2(w2.x, w2.x);
            u64 w1 = pack2(w2.y, w2.y);
            ffma2(acc00, w0, zq.x); ffma2(acc01, w0, zq.y);
            ffma2(acc10, w1, zq.x); ffma2(acc11, w1, zq.y);
        }
        float bias0 = sm->vb2s[2 * j], bias1 = sm->vb2s[2 * j + 1];
        float2 rA = unpack2(acc00);   // batches 4bq+0,+1 @ o0
        float2 rB = unpack2(acc01);   // batches 4bq+2,+3 @ o0
        float2 rC = unpack2(acc10);   // @ o1
        float2 rD = unpack2(acc11);
        const int b = 4 * bq;
        *(float2*)&sm->vloc[b + 0][2 * j] = make_float2(tanh_f(rA.x + bias0), tanh_f(rC.x + bias1));
        *(float2*)&sm->vloc[b + 1][2 * j] = make_float2(tanh_f(rA.y + bias0), tanh_f(rC.y + bias1));
        *(float2*)&sm->vloc[b + 2][2 * j] = make_float2(tanh_f(rB.x + bias0), tanh_f(rD.x + bias1));
        *(float2*)&sm->vloc[b + 3][2 * j] = make_float2(tanh_f(rB.y + bias0), tanh_f(rD.y + bias1));
    }

    // ---- layer 3 tail: slice outputs [256,264), warp w -> 1 output x 8 batches ----
    {
        const int w = tid >> 5, lane = tid & 31;
        const int oloc = OSL_MAIN + w;
        const int og = OSL * rank + oloc;
        float4 wv = *(const float4*)(vW2 + (size_t)og * W_DIM + 4 * lane);
        float s[BA];
        #pragma unroll
        for (int b = 0; b < BA; b++) {
            float4 zz = *(const float4*)&sm->z2c[b][4 * lane];
            s[b] = wv.x * zz.x + wv.y * zz.y + wv.z * zz.z + wv.w * zz.w;
        }
        #pragma unroll
        for (int off = 16; off; off >>= 1) {
            #pragma unroll
            for (int b = 0; b < BA; b++)
                s[b] += __shfl_xor_sync(0xffffffffu, s[b], off);
        }
        if (lane == 0) {
            float bias = sm->vb2s[oloc];
            #pragma unroll
            for (int b = 0; b < BA; b++)
                sm->vloc[b][oloc] = tanh_f(s[b] + bias);
        }
    }
    __syncthreads();
}

__global__ void __launch_bounds__(NTHR, 1) __cluster_dims__(P_CL, 1, 1)
cde_kernel(
    const float* __restrict__ ts,  const float* __restrict__ ys,
    const float* __restrict__ iW0, const float* __restrict__ ib0,
    const float* __restrict__ iW1, const float* __restrict__ ib1,
    const float* __restrict__ iW2, const float* __restrict__ ib2,
    const float* __restrict__ vW0, const float* __restrict__ vb0,
    const float* __restrict__ vW1, const float* __restrict__ vb1,
    const float* __restrict__ vW2, const float* __restrict__ vb2,
    const float* __restrict__ rW,  const float* __restrict__ rb,
    float* __restrict__ out)
{
    extern __shared__ float smraw[];
    Smem* sm = reinterpret_cast<Smem*>(smraw);
    const int tid  = threadIdx.x;
    const int rank = (int)cl_rank();          // 0..7
    const int b0   = (blockIdx.x >> 3) * BA;  // cluster batch group
    (void)vW0;

    // ---- stage resident weights ----
    for (int i = tid; i < W_DIM * OSL; i += NTHR) {
        int k = i / OSL, ol = i - k * OSL;
        sm->wsl[i] = g_vW2T[k * O_DIM + OSL * rank + ol];
    }
    for (int i = tid; i < W_DIM * W_DIM; i += NTHR) {
        int j = i >> 7, k = i & 127;
        sm->vW1p[j * 130 + k] = vW1[i];
    }
    if (tid < W_DIM) { sm->vb0[tid] = vb0[tid]; sm->vb1[tid] = vb1[tid]; }
    for (int i = tid; i < OSL; i += NTHR) sm->vb2s[i] = vb2[OSL * rank + i];

    // ---- initial x0 and per-thread dx state (b = tid>>5, c = tid&31) ----
    const int dxb = tid >> 5, dxc = tid & 31;
    float cury_r = ys[(size_t)(b0 + dxb) * T_LEN * D_IN + dxc];
    sm->dxv[0][dxb][dxc + 1] = cury_r;
    if (dxc == 0) sm->dxv[0][dxb][0] = ts[0];
    float pref_y = __ldg(&ys[(size_t)(b0 + dxb) * T_LEN * D_IN + D_IN + dxc]);
    float pref_t = __ldg(&ts[1]);
    __syncthreads();

    // ---- initial MLP (replicated; computes FULL y0 for all 8 batches) ----
    {
        const int j = tid & 127, bq = tid >> 7;
        #pragma unroll
        for (int i = 0; i < 4; i++) {
            int b = 4 * bq + i;
            float a = ib0[j];
            #pragma unroll
            for (int c = 0; c < C_DIM; c++) a += sm->dxv[0][b][c] * iW0[j * C_DIM + c];
            sm->z1[b][j] = fmaxf(a, 0.f);
        }
    }
    __syncthreads();
    {
        const int j = tid & 127, bq = tid >> 7;
        #pragma unroll
        for (int i = 0; i < 4; i++) {
            int b = 4 * bq + i;
            float a = ib1[j];
            #pragma unroll 8
            for (int k = 0; k < W_DIM; k++) a += sm->z1[b][k] * iW1[j * W_DIM + k];
            sm->z2c[b][j] = fmaxf(a, 0.f);
        }
    }
    __syncthreads();
    {
        const int h = tid & 63, g2 = tid >> 6;
        #pragma unroll
        for (int gb = 0; gb < 2; gb++) {
            int b = g2 + 4 * gb;
            float a = ib2[h];
            #pragma unroll 8
            for (int k = 0; k < W_DIM; k++) a += sm->z2c[b][k] * iW2[h * W_DIM + k];
            sm->yh[0][b][h] = a;
        }
    }
    __syncthreads();

    // owner state (threads 0..63): b = tid>>3, hl = tid&7, h = 8*rank + hl
    float y = 0.f, yhat_r = 0.f, sdot = 0.f;
    if (tid < 64) {
        int b = tid >> 3, hl = tid & 7;
        y = yhat_r = sm->yh[0][b][HSL * rank + hl];
    }

    // v0 = vf(ts[0], y0)
    vf_eval(sm, tid, rank, ts[0], 0, vW2);

    // ---- scan over 1023 steps ----
    float tprev = ts[0];
    for (int t = 1; t < T_LEN; t++) {
        const int par = t & 1;
        float t1 = pref_t;

        // dx = x[t] - x[t-1] into dxv[par] (prefetched values)
        {
            float nv = pref_y;
            sm->dxv[par][dxb][dxc + 1] = nv - cury_r;
            cury_r = nv;
            if (dxc == 0) sm->dxv[par][dxb][0] = t1 - tprev;
        }
        tprev = t1;
        if (t + 1 < T_LEN) {
            pref_y = __ldg(&ys[(size_t)(b0 + dxb) * T_LEN * D_IN
                               + (size_t)(t + 1) * D_IN + dxc]);
            pref_t = __ldg(&ts[t + 1]);
        }
        __syncthreads();

        // einsum1 on slice: s = v.dx ; yhat1 = 2y - yhat + s ; push to all 8 CTAs
        if (tid < 64) {
            int b = tid >> 3, hl = tid & 7;
            const float* vp = &sm->vloc[b][hl * C_DIM];
            const float* dp = sm->dxv[par][b];
            float a = 0.f;
            #pragma unroll
            for (int c = 0; c < C_DIM; c++) a += vp[c] * dp[c];
            sdot = a;
            float yh1 = 2.f * y - yhat_r + a;
            yhat_r = yh1;
            uint32_t addr = s2u(&sm->yh[par][b][HSL * rank + hl]);
            #pragma unroll
            for (int rr = 0; rr < P_CL; rr++) st_cluster(addr, rr, yh1);
        }
        CLUSTER_SYNC();   // yh[par] complete in every CTA

        // v1 = vf(t1, yhat1) into vloc
        vf_eval(sm, tid, rank, t1, par, vW2);

        // einsum2: y += 0.5 * (s + v1.dx)   (no trailing barrier: dxv parity-buffered)
        if (tid < 64) {
            int b = tid >> 3, hl = tid & 7;
            const float* vp = &sm->vloc[b][hl * C_DIM];
            const float* dp = sm->dxv[par][b];
            float a = 0.f;
            #pragma unroll
            for (int c = 0; c < C_DIM; c++) a += vp[c] * dp[c];
            y += 0.5f * (sdot + a);
        }
    }

    // ---- readout: out[b] = sum_h y[b][h]*rW[h] + rb ----
    __syncthreads();
    if (tid < 64) {
        int b = tid >> 3, hl = tid & 7;
        sm->red[b][hl] = y * rW[HSL * rank + hl];
    }
    __syncthreads();
    if (tid < BA) {
        float p = 0.f;
        #pragma unroll
        for (int hl = 0; hl < HSL; hl++) p += sm->red[tid][hl];
        uint32_t addr = s2u(&sm->pbuf[rank][tid]);
        st_cluster(addr, 0, p);   // gather at rank 0
    }
    CLUSTER_SYNC();
    if (rank == 0 && tid < BA) {
        float a = rb[0];
        #pragma unroll
        for (int r = 0; r < P_CL; r++) a += sm->pbuf[r][tid];
        out[b0 + tid] = a;
    }
    CLUSTER_SYNC();   // keep peer smem alive until all cluster traffic done
}

extern "C" void kernel_launch(void* const* d_in, const int* in_sizes, int n_in,
                              void* d_out, int out_size) {
    (void)in_sizes; (void)n_in; (void)out_size;
    const float* ts  = (const float*)d_in[0];
    const float* ys  = (const float*)d_in[1];
    const float* iW0 = (const float*)d_in[2];
    const float* ib0 = (const float*)d_in[3];
    const float* iW1 = (const float*)d_in[4];
    const float* ib1 = (const float*)d_in[5];
    const float* iW2 = (const float*)d_in[6];
    const float* ib2 = (const float*)d_in[7];
    const float* vW0 = (const float*)d_in[8];
    const float* vb0 = (const float*)d_in[9];
    const float* vW1 = (const float*)d_in[10];
    const float* vb1 = (const float*)d_in[11];
    const float* vW2 = (const float*)d_in[12];
    const float* vb2 = (const float*)d_in[13];
    const float* rW  = (const float*)d_in[14];
    const float* rb  = (const float*)d_in[15];
    float* out = (float*)d_out;

    cudaFuncSetAttribute(cde_kernel, cudaFuncAttributeMaxDynamicSharedMemorySize,
                         (int)sizeof(Smem));

    cde_prep_kernel<<<(W_DIM * O_DIM + 255) / 256, 256>>>(vW2, vW0);
    cde_kernel<<<NCTA, NTHR, sizeof(Smem)>>>(
        ts, ys, iW0, ib0, iW1, ib1, iW2, ib2,
        vW0, vb0, vW1, vb1, vW2, vb2, rW, rb, out);
}